// round 6
// baseline (speedup 1.0000x reference)
#include <cuda_runtime.h>
#include <cuda_bf16.h>

#define NT 4096
#define NBATCH 256
#define TPB 512
#define SPT 8          // time steps per precompute thread (4096/512)

// Scratch: [b][u][t] -> (xi, xc, xo, f)  : 256*8*4096 float4 = 134MB
__device__ float4 g_gates[(size_t)NBATCH * 8 * NT];

static __device__ __forceinline__ float tanha(float x) {
    float y; asm("tanh.approx.f32 %0, %1;" : "=f"(y) : "f"(x)); return y;
}
static __device__ __forceinline__ float sigm(float x) {   // exact identity; approx only via TANH
    return fmaf(tanha(0.5f * x), 0.5f, 0.5f);
}

#define FMA4(acc, s, v) do { \
    (acc).x = fmaf((s), (v).x, (acc).x); (acc).y = fmaf((s), (v).y, (acc).y); \
    (acc).z = fmaf((s), (v).z, (acc).z); (acc).w = fmaf((s), (v).w, (acc).w); } while (0)

// ============================================================================
// Kernel 1: parallel signature + forget gate + x-projections.
// L1_t = p_t - p_0 (telescoped, exact). L2_t = C_t - p0 (x) L1_t with
// C_t = sum_{s<=t} pbar_s (x) dx_s  -> a plain 16-component prefix sum,
// computed with a block-level scan (one block per batch).
// ============================================================================
__global__ void __launch_bounds__(TPB) pre_kernel(
    const float* __restrict__ inp,   // (256, 4096, 3)
    const float* __restrict__ ik,    // (3, 24)
    const float* __restrict__ fk,    // (21, 8)
    const float* __restrict__ bias)  // (32)
{
    __shared__ float4 sF4[42];    // fk: comp c -> sF4[2c], sF4[2c+1]   (21 x 8)
    __shared__ float4 sIk4[18];   // ik: row d -> 6 float4 (i:0-1, c:2-3, o:4-5)
    __shared__ float4 sB4[8];     // bias: bi(0,1) bf(2,3) bc(4,5) bo(6,7)
    __shared__ float  wsum[16][16];   // [warp][comp]

    const int b = blockIdx.x, tid = threadIdx.x;
    if (tid < 42)      sF4[tid]      = ((const float4*)fk)[tid];
    else if (tid < 60) sIk4[tid-42]  = ((const float4*)ik)[tid-42];
    else if (tid < 68) sB4[tid-60]   = ((const float4*)bias)[tid-60];
    __syncthreads();

    const float DX0 = 1.0f / 4095.0f;
    const int t0 = tid * SPT;
    const float* __restrict__ xb = inp + (size_t)b * NT * 3;

    // path x for t = t0-1 .. t0+7  (m = 0..8); clamp only hits unused slot of tid 0
    float x0[9], x1[9], x2[9];
#pragma unroll
    for (int m = 0; m < 9; m++) {
        int t = t0 - 1 + m; if (t < 0) t = 0;
        const float* p = xb + t * 3;
        x0[m] = p[0]; x1[m] = p[1]; x2[m] = p[2];
    }
    const float bx0 = xb[0], bx1 = xb[1], bx2 = xb[2];   // p_0 (space comps; time comp = 0)

    // ---- pass 1: thread-local sum of M_s = pbar (x) dx over own 8 steps ----
    float T[16];
#pragma unroll
    for (int c = 0; c < 16; c++) T[c] = 0.f;
#pragma unroll
    for (int k = 0; k < SPT; k++) {
        const int s = t0 + k;
        const float w = (s >= 1) ? 1.f : 0.f;            // s=0 contributes nothing
        float d1 = (x0[k+1]-x0[k])*w, d2 = (x1[k+1]-x1[k])*w, d3 = (x2[k+1]-x2[k])*w;
        float d0 = DX0 * w;
        float pb0 = ((float)s - 0.5f) * DX0;
        float pb1 = 0.5f*(x0[k+1]+x0[k]), pb2 = 0.5f*(x1[k+1]+x1[k]), pb3 = 0.5f*(x2[k+1]+x2[k]);
        T[0] =fmaf(pb0,d0,T[0]);  T[1] =fmaf(pb0,d1,T[1]);  T[2] =fmaf(pb0,d2,T[2]);  T[3] =fmaf(pb0,d3,T[3]);
        T[4] =fmaf(pb1,d0,T[4]);  T[5] =fmaf(pb1,d1,T[5]);  T[6] =fmaf(pb1,d2,T[6]);  T[7] =fmaf(pb1,d3,T[7]);
        T[8] =fmaf(pb2,d0,T[8]);  T[9] =fmaf(pb2,d1,T[9]);  T[10]=fmaf(pb2,d2,T[10]); T[11]=fmaf(pb2,d3,T[11]);
        T[12]=fmaf(pb3,d0,T[12]); T[13]=fmaf(pb3,d1,T[13]); T[14]=fmaf(pb3,d2,T[14]); T[15]=fmaf(pb3,d3,T[15]);
    }

    // ---- block scan (exclusive for this thread) ----
    float inc[16];
#pragma unroll
    for (int c = 0; c < 16; c++) inc[c] = T[c];
    const int lane = tid & 31, wid = tid >> 5;
#pragma unroll
    for (int off = 1; off < 32; off <<= 1) {
#pragma unroll
        for (int c = 0; c < 16; c++) {
            float v = __shfl_up_sync(0xffffffffu, inc[c], off);
            if (lane >= off) inc[c] += v;
        }
    }
    if (lane == 31) {
#pragma unroll
        for (int c = 0; c < 16; c++) wsum[wid][c] = inc[c];
    }
    __syncthreads();
    if (tid < 16) {                       // comp = tid: serial exclusive scan over 16 warps
        float run = 0.f;
        for (int wv = 0; wv < 16; wv++) { float v = wsum[wv][tid]; wsum[wv][tid] = run; run += v; }
    }
    __syncthreads();
    float C[16];
#pragma unroll
    for (int c = 0; c < 16; c++) C[c] = wsum[wid][c] + (inc[c] - T[c]);

    // ---- pass 2: walk own steps, emit (xi, xc, xo, f) per unit ----
    float4* __restrict__ gout = g_gates + (size_t)b * 8 * NT;
#pragma unroll
    for (int k = 0; k < SPT; k++) {
        const int s = t0 + k;
        const float w = (s >= 1) ? 1.f : 0.f;
        float d1 = (x0[k+1]-x0[k])*w, d2 = (x1[k+1]-x1[k])*w, d3 = (x2[k+1]-x2[k])*w;
        float d0 = DX0 * w;
        float pb0 = ((float)s - 0.5f) * DX0;
        float pb1 = 0.5f*(x0[k+1]+x0[k]), pb2 = 0.5f*(x1[k+1]+x1[k]), pb3 = 0.5f*(x2[k+1]+x2[k]);
        C[0] =fmaf(pb0,d0,C[0]);  C[1] =fmaf(pb0,d1,C[1]);  C[2] =fmaf(pb0,d2,C[2]);  C[3] =fmaf(pb0,d3,C[3]);
        C[4] =fmaf(pb1,d0,C[4]);  C[5] =fmaf(pb1,d1,C[5]);  C[6] =fmaf(pb1,d2,C[6]);  C[7] =fmaf(pb1,d3,C[7]);
        C[8] =fmaf(pb2,d0,C[8]);  C[9] =fmaf(pb2,d1,C[9]);  C[10]=fmaf(pb2,d2,C[10]); C[11]=fmaf(pb2,d3,C[11]);
        C[12]=fmaf(pb3,d0,C[12]); C[13]=fmaf(pb3,d1,C[13]); C[14]=fmaf(pb3,d2,C[14]); C[15]=fmaf(pb3,d3,C[15]);

        // signature of step s
        float L1_0 = (float)s * DX0;
        float L1_1 = x0[k+1] - bx0, L1_2 = x1[k+1] - bx1, L1_3 = x2[k+1] - bx2;
        float sg[21];
        sg[0] = 1.f;
        sg[1] = L1_0; sg[2] = L1_1; sg[3] = L1_2; sg[4] = L1_3;
        sg[5]  = C[0];                  sg[6]  = C[1];                  sg[7]  = C[2];                  sg[8]  = C[3];
        sg[9]  = fmaf(-bx0,L1_0,C[4]);  sg[10] = fmaf(-bx0,L1_1,C[5]);  sg[11] = fmaf(-bx0,L1_2,C[6]);  sg[12] = fmaf(-bx0,L1_3,C[7]);
        sg[13] = fmaf(-bx1,L1_0,C[8]);  sg[14] = fmaf(-bx1,L1_1,C[9]);  sg[15] = fmaf(-bx1,L1_2,C[10]); sg[16] = fmaf(-bx1,L1_3,C[11]);
        sg[17] = fmaf(-bx2,L1_0,C[12]); sg[18] = fmaf(-bx2,L1_1,C[13]); sg[19] = fmaf(-bx2,L1_2,C[14]); sg[20] = fmaf(-bx2,L1_3,C[15]);
        float norm = 1.0f;
        if (s >= 1) norm = __fdividef(4095.0f, (float)s);
        else {                                    // t=0: sig = [1, 0, ...], unnormalized
#pragma unroll
            for (int c2 = 1; c2 < 21; c2++) sg[c2] = 0.f;
        }

        // forget-gate pre-activation for 8 units
        float4 aA = make_float4(0.f,0.f,0.f,0.f), aB = make_float4(0.f,0.f,0.f,0.f);
#pragma unroll
        for (int c2 = 0; c2 < 21; c2++) {
            float sc = sg[c2];
            FMA4(aA, sc, sF4[2*c2]);
            FMA4(aB, sc, sF4[2*c2+1]);
        }
        float fg0 = sigm(fmaf(aA.x, norm, sB4[2].x));
        float fg1 = sigm(fmaf(aA.y, norm, sB4[2].y));
        float fg2 = sigm(fmaf(aA.z, norm, sB4[2].z));
        float fg3 = sigm(fmaf(aA.w, norm, sB4[2].w));
        float fg4 = sigm(fmaf(aB.x, norm, sB4[3].x));
        float fg5 = sigm(fmaf(aB.y, norm, sB4[3].y));
        float fg6 = sigm(fmaf(aB.z, norm, sB4[3].z));
        float fg7 = sigm(fmaf(aB.w, norm, sB4[3].w));

        // x-projections at t = s (biases folded in)
        float xc0 = x0[k+1], xc1 = x1[k+1], xc2 = x2[k+1];
        float4 xiA = sB4[0], xiB = sB4[1], xgA = sB4[4], xgB = sB4[5], xoA = sB4[6], xoB = sB4[7];
        FMA4(xiA, xc0, sIk4[0]);  FMA4(xiB, xc0, sIk4[1]);
        FMA4(xgA, xc0, sIk4[2]);  FMA4(xgB, xc0, sIk4[3]);
        FMA4(xoA, xc0, sIk4[4]);  FMA4(xoB, xc0, sIk4[5]);
        FMA4(xiA, xc1, sIk4[6]);  FMA4(xiB, xc1, sIk4[7]);
        FMA4(xgA, xc1, sIk4[8]);  FMA4(xgB, xc1, sIk4[9]);
        FMA4(xoA, xc1, sIk4[10]); FMA4(xoB, xc1, sIk4[11]);
        FMA4(xiA, xc2, sIk4[12]); FMA4(xiB, xc2, sIk4[13]);
        FMA4(xgA, xc2, sIk4[14]); FMA4(xgB, xc2, sIk4[15]);
        FMA4(xoA, xc2, sIk4[16]); FMA4(xoB, xc2, sIk4[17]);

        gout[0*NT + s] = make_float4(xiA.x, xgA.x, xoA.x, fg0);
        gout[1*NT + s] = make_float4(xiA.y, xgA.y, xoA.y, fg1);
        gout[2*NT + s] = make_float4(xiA.z, xgA.z, xoA.z, fg2);
        gout[3*NT + s] = make_float4(xiA.w, xgA.w, xoA.w, fg3);
        gout[4*NT + s] = make_float4(xiB.x, xgB.x, xoB.x, fg4);
        gout[5*NT + s] = make_float4(xiB.y, xgB.y, xoB.y, fg5);
        gout[6*NT + s] = make_float4(xiB.z, xgB.z, xoB.z, fg6);
        gout[7*NT + s] = make_float4(xiB.w, xgB.w, xoB.w, fg7);
    }
}

// ============================================================================
// Kernel 2: pure LSTM recurrence. ~48 instrs/step, chain-bound.
// ============================================================================
#define RSTEP(T_, J) do { \
    float4 g = r##J; \
    { int tp_ = (T_) + 8; if (tp_ > NT - 1) tp_ = NT - 1; r##J = __ldg(gp + tp_); } \
    float h0 = __shfl_sync(0xFFu, h, 0); \
    float h1 = __shfl_sync(0xFFu, h, 1); \
    float h2 = __shfl_sync(0xFFu, h, 2); \
    float h3 = __shfl_sync(0xFFu, h, 3); \
    float h4 = __shfl_sync(0xFFu, h, 4); \
    float h5 = __shfl_sync(0xFFu, h, 5); \
    float h6 = __shfl_sync(0xFFu, h, 6); \
    float h7 = __shfl_sync(0xFFu, h, 7); \
    float giA = fmaf(h3,Ri3, fmaf(h2,Ri2, fmaf(h1,Ri1, fmaf(h0,Ri0, g.x)))); \
    float giB = fmaf(h7,Ri7, fmaf(h6,Ri6, fmaf(h5,Ri5, h4 * Ri4))); \
    float gcA = fmaf(h3,Rc3, fmaf(h2,Rc2, fmaf(h1,Rc1, fmaf(h0,Rc0, g.y)))); \
    float gcB = fmaf(h7,Rc7, fmaf(h6,Rc6, fmaf(h5,Rc5, h4 * Rc4))); \
    float goA = fmaf(h3,Ro3, fmaf(h2,Ro2, fmaf(h1,Ro1, fmaf(h0,Ro0, g.z)))); \
    float goB = fmaf(h7,Ro7, fmaf(h6,Ro6, fmaf(h5,Ro5, h4 * Ro4))); \
    float vi = sigm(giA + giB); \
    float vc = tanha(gcA + gcB); \
    float vo = sigm(goA + goB); \
    c = fmaf(g.w, c, vi * vc); \
    h = vo * tanha(c); \
    op[(size_t)(T_) * 8] = h; \
} while (0)

__global__ void __launch_bounds__(32, 1) rec_kernel(
    const float* __restrict__ rk,    // (8, 24)
    float* __restrict__ out)         // (256, 4096, 8)
{
    const int b = blockIdx.x;
    const int u = threadIdx.x;
    if (u >= 8) return;              // 8 active lanes; shfl mask 0xFF

    const float Ri0=rk[0*24+u], Ri1=rk[1*24+u], Ri2=rk[2*24+u], Ri3=rk[3*24+u];
    const float Ri4=rk[4*24+u], Ri5=rk[5*24+u], Ri6=rk[6*24+u], Ri7=rk[7*24+u];
    const float Rc0=rk[0*24+8+u], Rc1=rk[1*24+8+u], Rc2=rk[2*24+8+u], Rc3=rk[3*24+8+u];
    const float Rc4=rk[4*24+8+u], Rc5=rk[5*24+8+u], Rc6=rk[6*24+8+u], Rc7=rk[7*24+8+u];
    const float Ro0=rk[0*24+16+u], Ro1=rk[1*24+16+u], Ro2=rk[2*24+16+u], Ro3=rk[3*24+16+u];
    const float Ro4=rk[4*24+16+u], Ro5=rk[5*24+16+u], Ro6=rk[6*24+16+u], Ro7=rk[7*24+16+u];

    const float4* __restrict__ gp = g_gates + ((size_t)b * 8 + u) * NT;
    float* __restrict__ op = out + (size_t)b * NT * 8 + u;

    float h, c;
    // t = 0: h_prev = c_prev = 0 -> gates are the precomputed x-projections
    {
        float4 g0 = __ldg(gp);
        c = sigm(g0.x) * tanha(g0.y);
        h = sigm(g0.z) * tanha(c);
        op[0] = h;
    }

    // ring fill: slot j <- t = 1+j
    float4 r0 = __ldg(gp+1), r1 = __ldg(gp+2), r2 = __ldg(gp+3), r3 = __ldg(gp+4);
    float4 r4 = __ldg(gp+5), r5 = __ldg(gp+6), r6 = __ldg(gp+7), r7 = __ldg(gp+8);

    // main loop: t = 1 .. 4088
    for (int blk = 0; blk < 511; blk++) {
        const int t = 1 + blk * 8;
        RSTEP(t    , 0); RSTEP(t + 1, 1); RSTEP(t + 2, 2); RSTEP(t + 3, 3);
        RSTEP(t + 4, 4); RSTEP(t + 5, 5); RSTEP(t + 6, 6); RSTEP(t + 7, 7);
    }
    // tail: t = 4089 .. 4095 (slots 0..6)
    RSTEP(4089, 0); RSTEP(4090, 1); RSTEP(4091, 2); RSTEP(4092, 3);
    RSTEP(4093, 4); RSTEP(4094, 5); RSTEP(4095, 6);
}

extern "C" void kernel_launch(void* const* d_in, const int* in_sizes, int n_in,
                              void* d_out, int out_size)
{
    const float* inp  = (const float*)d_in[0];   // inputs (256,4096,3)
    const float* ik   = (const float*)d_in[1];   // input_kernel (3,24)
    const float* rk   = (const float*)d_in[2];   // recurrent_kernel (8,24)
    const float* fk   = (const float*)d_in[3];   // forget_kernel (21,8)
    const float* bias = (const float*)d_in[4];   // bias (32)
    float* out = (float*)d_out;                  // (256,4096,8) f32

    pre_kernel<<<NBATCH, TPB>>>(inp, ik, fk, bias);
    rec_kernel<<<NBATCH, 32>>>(rk, out);
}

// round 7
// speedup vs baseline: 1.6899x; 1.6899x over previous
#include <cuda_runtime.h>
#include <cuda_bf16.h>

#define NT 4096
#define NBATCH 256
#define TPB 512
#define SPT 8          // time steps per scan thread (4096/512)

// Scratch: [b][u][t] -> (xi', xc, xo', f)  (xi', xo' pre-scaled by 0.5, biases folded)
__device__ float4 g_gates[(size_t)NBATCH * 8 * NT];
// Chunk-exclusive prefix of the 16 L2 accumulators: [b][chunk][16]
__device__ float  g_cbase[(size_t)NBATCH * TPB * 16];

static __device__ __forceinline__ float tanha(float x) {
    float y; asm("tanh.approx.f32 %0, %1;" : "=f"(y) : "f"(x)); return y;
}
static __device__ __forceinline__ float sigm(float x) {
    return fmaf(tanha(0.5f * x), 0.5f, 0.5f);
}

#define FMA4(acc, s, v) do { \
    (acc).x = fmaf((s), (v).x, (acc).x); (acc).y = fmaf((s), (v).y, (acc).y); \
    (acc).z = fmaf((s), (v).z, (acc).z); (acc).w = fmaf((s), (v).w, (acc).w); } while (0)

// ============================================================================
// Kernel 1a: block scan of the 16 L2-term accumulators (chunk granularity).
// C_t = sum_{s<=t} pbar_s (x) dx_s ; this kernel writes each thread-chunk's
// EXCLUSIVE prefix to g_cbase. Light register load -> no spills.
// ============================================================================
__global__ void __launch_bounds__(TPB) scan_kernel(const float* __restrict__ inp)
{
    __shared__ float wsum[16][16];
    const int b = blockIdx.x, tid = threadIdx.x;
    const float DX0 = 1.0f / 4095.0f;
    const int t0 = tid * SPT;
    const float* __restrict__ xb = inp + (size_t)b * NT * 3;

    float T[16];
#pragma unroll
    for (int c = 0; c < 16; c++) T[c] = 0.f;
    {
        int tm = t0 - 1; if (tm < 0) tm = 0;
        float a0 = xb[tm*3], a1 = xb[tm*3+1], a2 = xb[tm*3+2];
#pragma unroll
        for (int k = 0; k < SPT; k++) {
            const int s = t0 + k;
            const float* p = xb + s * 3;
            float n0 = p[0], n1 = p[1], n2 = p[2];
            const float w = (s >= 1) ? 1.f : 0.f;
            float d1 = (n0-a0)*w, d2 = (n1-a1)*w, d3 = (n2-a2)*w, d0 = DX0*w;
            float pb0 = ((float)s - 0.5f) * DX0;
            float pb1 = 0.5f*(n0+a0), pb2 = 0.5f*(n1+a1), pb3 = 0.5f*(n2+a2);
            T[0] =fmaf(pb0,d0,T[0]);  T[1] =fmaf(pb0,d1,T[1]);  T[2] =fmaf(pb0,d2,T[2]);  T[3] =fmaf(pb0,d3,T[3]);
            T[4] =fmaf(pb1,d0,T[4]);  T[5] =fmaf(pb1,d1,T[5]);  T[6] =fmaf(pb1,d2,T[6]);  T[7] =fmaf(pb1,d3,T[7]);
            T[8] =fmaf(pb2,d0,T[8]);  T[9] =fmaf(pb2,d1,T[9]);  T[10]=fmaf(pb2,d2,T[10]); T[11]=fmaf(pb2,d3,T[11]);
            T[12]=fmaf(pb3,d0,T[12]); T[13]=fmaf(pb3,d1,T[13]); T[14]=fmaf(pb3,d2,T[14]); T[15]=fmaf(pb3,d3,T[15]);
            a0 = n0; a1 = n1; a2 = n2;
        }
    }
    float inc[16];
#pragma unroll
    for (int c = 0; c < 16; c++) inc[c] = T[c];
    const int lane = tid & 31, wid = tid >> 5;
#pragma unroll
    for (int off = 1; off < 32; off <<= 1) {
#pragma unroll
        for (int c = 0; c < 16; c++) {
            float v = __shfl_up_sync(0xffffffffu, inc[c], off);
            if (lane >= off) inc[c] += v;
        }
    }
    if (lane == 31) {
#pragma unroll
        for (int c = 0; c < 16; c++) wsum[wid][c] = inc[c];
    }
    __syncthreads();
    if (tid < 16) {
        float run = 0.f;
        for (int wv = 0; wv < 16; wv++) { float v = wsum[wv][tid]; wsum[wv][tid] = run; run += v; }
    }
    __syncthreads();
    float* __restrict__ cb = g_cbase + ((size_t)b * TPB + tid) * 16;
#pragma unroll
    for (int c = 0; c < 16; c++) cb[c] = wsum[wid][c] + (inc[c] - T[c]);
}

// ============================================================================
// Kernel 1b: one thread per (b, s). Rebuild C_s from its chunk base (<=8 local
// terms), form the signature, emit (0.5(xi+bi), xc+bc, 0.5(xo+bo), f) per unit.
// Coalesced writes (consecutive threads = consecutive s).
// ============================================================================
__global__ void __launch_bounds__(TPB) emit_kernel(
    const float* __restrict__ inp,   // (256, 4096, 3)
    const float* __restrict__ ik,    // (3, 24)
    const float* __restrict__ fk,    // (21, 8)
    const float* __restrict__ bias)  // (32)
{
    __shared__ float4 sF4[42];
    __shared__ float4 sIk4[18];
    __shared__ float4 sB4[8];
    const int tid = threadIdx.x;
    const int b = blockIdx.x >> 3;
    const int s = ((blockIdx.x & 7) << 9) + tid;       // 8 chunks of 512 per batch
    if (tid < 42)      sF4[tid]     = ((const float4*)fk)[tid];
    else if (tid < 60) sIk4[tid-42] = ((const float4*)ik)[tid-42];
    else if (tid < 68) sB4[tid-60]  = ((const float4*)bias)[tid-60];
    __syncthreads();

    const float DX0 = 1.0f / 4095.0f;
    const float* __restrict__ xb = inp + (size_t)b * NT * 3;
    const int j = s >> 3;                               // scan chunk
    const int t0 = j * SPT;

    float C[16];
    {
        const float* __restrict__ cb = g_cbase + ((size_t)b * TPB + j) * 16;
#pragma unroll
        for (int c = 0; c < 16; c++) C[c] = cb[c];
    }
    // accumulate local terms k = t0 .. s (predicated, uniform 8 iterations)
    {
        int tm = t0 - 1; if (tm < 0) tm = 0;
        float a0 = xb[tm*3], a1 = xb[tm*3+1], a2 = xb[tm*3+2];
#pragma unroll
        for (int k0 = 0; k0 < SPT; k0++) {
            const int k = t0 + k0;
            const float* p = xb + k * 3;
            float n0 = p[0], n1 = p[1], n2 = p[2];
            const float w = (k >= 1 && k <= s) ? 1.f : 0.f;
            float d1 = (n0-a0)*w, d2 = (n1-a1)*w, d3 = (n2-a2)*w, d0 = DX0*w;
            float pb0 = ((float)k - 0.5f) * DX0;
            float pb1 = 0.5f*(n0+a0), pb2 = 0.5f*(n1+a1), pb3 = 0.5f*(n2+a2);
            C[0] =fmaf(pb0,d0,C[0]);  C[1] =fmaf(pb0,d1,C[1]);  C[2] =fmaf(pb0,d2,C[2]);  C[3] =fmaf(pb0,d3,C[3]);
            C[4] =fmaf(pb1,d0,C[4]);  C[5] =fmaf(pb1,d1,C[5]);  C[6] =fmaf(pb1,d2,C[6]);  C[7] =fmaf(pb1,d3,C[7]);
            C[8] =fmaf(pb2,d0,C[8]);  C[9] =fmaf(pb2,d1,C[9]);  C[10]=fmaf(pb2,d2,C[10]); C[11]=fmaf(pb2,d3,C[11]);
            C[12]=fmaf(pb3,d0,C[12]); C[13]=fmaf(pb3,d1,C[13]); C[14]=fmaf(pb3,d2,C[14]); C[15]=fmaf(pb3,d3,C[15]);
            a0 = n0; a1 = n1; a2 = n2;
        }
    }

    const float bx0 = xb[0], bx1 = xb[1], bx2 = xb[2];   // p_0 (space comps)
    const float xs0 = xb[s*3], xs1 = xb[s*3+1], xs2 = xb[s*3+2];

    // signature at step s: L1 telescoped, L2 = C - p0 (x) L1
    float L1_0 = (float)s * DX0;
    float L1_1 = xs0 - bx0, L1_2 = xs1 - bx1, L1_3 = xs2 - bx2;
    float sg[21];
    sg[0] = 1.f;
    sg[1] = L1_0; sg[2] = L1_1; sg[3] = L1_2; sg[4] = L1_3;
    sg[5]  = C[0];                  sg[6]  = C[1];                  sg[7]  = C[2];                  sg[8]  = C[3];
    sg[9]  = fmaf(-bx0,L1_0,C[4]);  sg[10] = fmaf(-bx0,L1_1,C[5]);  sg[11] = fmaf(-bx0,L1_2,C[6]);  sg[12] = fmaf(-bx0,L1_3,C[7]);
    sg[13] = fmaf(-bx1,L1_0,C[8]);  sg[14] = fmaf(-bx1,L1_1,C[9]);  sg[15] = fmaf(-bx1,L1_2,C[10]); sg[16] = fmaf(-bx1,L1_3,C[11]);
    sg[17] = fmaf(-bx2,L1_0,C[12]); sg[18] = fmaf(-bx2,L1_1,C[13]); sg[19] = fmaf(-bx2,L1_2,C[14]); sg[20] = fmaf(-bx2,L1_3,C[15]);
    float norm = 1.0f;
    if (s >= 1) norm = __fdividef(4095.0f, (float)s);
    else {
#pragma unroll
        for (int c2 = 1; c2 < 21; c2++) sg[c2] = 0.f;
    }

    float4 aA = make_float4(0.f,0.f,0.f,0.f), aB = make_float4(0.f,0.f,0.f,0.f);
#pragma unroll
    for (int c2 = 0; c2 < 21; c2++) {
        float sc = sg[c2];
        FMA4(aA, sc, sF4[2*c2]);
        FMA4(aB, sc, sF4[2*c2+1]);
    }
    float fg0 = sigm(fmaf(aA.x, norm, sB4[2].x));
    float fg1 = sigm(fmaf(aA.y, norm, sB4[2].y));
    float fg2 = sigm(fmaf(aA.z, norm, sB4[2].z));
    float fg3 = sigm(fmaf(aA.w, norm, sB4[2].w));
    float fg4 = sigm(fmaf(aB.x, norm, sB4[3].x));
    float fg5 = sigm(fmaf(aB.y, norm, sB4[3].y));
    float fg6 = sigm(fmaf(aB.z, norm, sB4[3].z));
    float fg7 = sigm(fmaf(aB.w, norm, sB4[3].w));

    float4 xiA = sB4[0], xiB = sB4[1], xgA = sB4[4], xgB = sB4[5], xoA = sB4[6], xoB = sB4[7];
    FMA4(xiA, xs0, sIk4[0]);  FMA4(xiB, xs0, sIk4[1]);
    FMA4(xgA, xs0, sIk4[2]);  FMA4(xgB, xs0, sIk4[3]);
    FMA4(xoA, xs0, sIk4[4]);  FMA4(xoB, xs0, sIk4[5]);
    FMA4(xiA, xs1, sIk4[6]);  FMA4(xiB, xs1, sIk4[7]);
    FMA4(xgA, xs1, sIk4[8]);  FMA4(xgB, xs1, sIk4[9]);
    FMA4(xoA, xs1, sIk4[10]); FMA4(xoB, xs1, sIk4[11]);
    FMA4(xiA, xs2, sIk4[12]); FMA4(xiB, xs2, sIk4[13]);
    FMA4(xgA, xs2, sIk4[14]); FMA4(xgB, xs2, sIk4[15]);
    FMA4(xoA, xs2, sIk4[16]); FMA4(xoB, xs2, sIk4[17]);

    float4* __restrict__ gout = g_gates + (size_t)b * 8 * NT;
    gout[0*NT + s] = make_float4(0.5f*xiA.x, xgA.x, 0.5f*xoA.x, fg0);
    gout[1*NT + s] = make_float4(0.5f*xiA.y, xgA.y, 0.5f*xoA.y, fg1);
    gout[2*NT + s] = make_float4(0.5f*xiA.z, xgA.z, 0.5f*xoA.z, fg2);
    gout[3*NT + s] = make_float4(0.5f*xiA.w, xgA.w, 0.5f*xoA.w, fg3);
    gout[4*NT + s] = make_float4(0.5f*xiB.x, xgB.x, 0.5f*xoB.x, fg4);
    gout[5*NT + s] = make_float4(0.5f*xiB.y, xgB.y, 0.5f*xoB.y, fg5);
    gout[6*NT + s] = make_float4(0.5f*xiB.z, xgB.z, 0.5f*xoB.z, fg6);
    gout[7*NT + s] = make_float4(0.5f*xiB.w, xgB.w, 0.5f*xoB.w, fg7);
}

// ============================================================================
// Kernel 2: LSTM recurrence. smem h-broadcast (STS + BAR(3cyc) + 2x LDS.128),
// 4 batches per warp as lane groups (pure SIMD). 0.5-sigmoid folded into
// weights; f*c computed off-chain.
// ============================================================================
#define RSTEP(T_, J) do { \
    hbuf[lane] = h; \
    __syncthreads(); \
    float4 hA = *(const float4*)&hbuf[g * 8]; \
    float4 hB = *(const float4*)&hbuf[g * 8 + 4]; \
    float4 gt = r##J; \
    { int tp_ = (T_) + 8; if (tp_ > NT - 1) tp_ = NT - 1; r##J = __ldg(gp + tp_); } \
    float fc = gt.w * c; \
    float giA = fmaf(hA.w,Ri3, fmaf(hA.z,Ri2, fmaf(hA.y,Ri1, fmaf(hA.x,Ri0, gt.x)))); \
    float giB = fmaf(hB.w,Ri7, fmaf(hB.z,Ri6, fmaf(hB.y,Ri5, hB.x * Ri4))); \
    float gcA = fmaf(hA.w,Rc3, fmaf(hA.z,Rc2, fmaf(hA.y,Rc1, fmaf(hA.x,Rc0, gt.y)))); \
    float gcB = fmaf(hB.w,Rc7, fmaf(hB.z,Rc6, fmaf(hB.y,Rc5, hB.x * Rc4))); \
    float goA = fmaf(hA.w,Ro3, fmaf(hA.z,Ro2, fmaf(hA.y,Ro1, fmaf(hA.x,Ro0, gt.z)))); \
    float goB = fmaf(hB.w,Ro7, fmaf(hB.z,Ro6, fmaf(hB.y,Ro5, hB.x * Ro4))); \
    float vi = fmaf(tanha(giA + giB), 0.5f, 0.5f); \
    float vc = tanha(gcA + gcB); \
    float vo = fmaf(tanha(goA + goB), 0.5f, 0.5f); \
    c = fmaf(vi, vc, fc); \
    h = vo * tanha(c); \
    op[(size_t)(T_) * 8] = h; \
} while (0)

__global__ void __launch_bounds__(32, 1) rec_kernel(
    const float* __restrict__ rk,    // (8, 24)
    float* __restrict__ out)         // (256, 4096, 8)
{
    __shared__ __align__(16) float hbuf[32];
    const int lane = threadIdx.x;
    const int u = lane & 7;          // LSTM unit
    const int g = lane >> 3;         // batch group within warp
    const int b = blockIdx.x * 4 + g;

    // Ri/Ro pre-scaled by 0.5 (sigmoid identity); Rc unscaled (tanh gate)
    const float Ri0=0.5f*rk[0*24+u], Ri1=0.5f*rk[1*24+u], Ri2=0.5f*rk[2*24+u], Ri3=0.5f*rk[3*24+u];
    const float Ri4=0.5f*rk[4*24+u], Ri5=0.5f*rk[5*24+u], Ri6=0.5f*rk[6*24+u], Ri7=0.5f*rk[7*24+u];
    const float Rc0=rk[0*24+8+u], Rc1=rk[1*24+8+u], Rc2=rk[2*24+8+u], Rc3=rk[3*24+8+u];
    const float Rc4=rk[4*24+8+u], Rc5=rk[5*24+8+u], Rc6=rk[6*24+8+u], Rc7=rk[7*24+8+u];
    const float Ro0=0.5f*rk[0*24+16+u], Ro1=0.5f*rk[1*24+16+u], Ro2=0.5f*rk[2*24+16+u], Ro3=0.5f*rk[3*24+16+u];
    const float Ro4=0.5f*rk[4*24+16+u], Ro5=0.5f*rk[5*24+16+u], Ro6=0.5f*rk[6*24+16+u], Ro7=0.5f*rk[7*24+16+u];

    const float4* __restrict__ gp = g_gates + ((size_t)b * 8 + u) * NT;
    float* __restrict__ op = out + (size_t)b * NT * 8 + u;

    float h, c;
    // t = 0: h_prev = c_prev = 0; stored .x/.z already 0.5-scaled w/ bias
    {
        float4 g0 = __ldg(gp);
        float vi = fmaf(tanha(g0.x), 0.5f, 0.5f);
        float vc = tanha(g0.y);
        float vo = fmaf(tanha(g0.z), 0.5f, 0.5f);
        c = vi * vc;
        h = vo * tanha(c);
        op[0] = h;
    }

    float4 r0 = __ldg(gp+1), r1 = __ldg(gp+2), r2 = __ldg(gp+3), r3 = __ldg(gp+4);
    float4 r4 = __ldg(gp+5), r5 = __ldg(gp+6), r6 = __ldg(gp+7), r7 = __ldg(gp+8);

    for (int blk = 0; blk < 511; blk++) {
        const int t = 1 + blk * 8;
        RSTEP(t    , 0); RSTEP(t + 1, 1); RSTEP(t + 2, 2); RSTEP(t + 3, 3);
        RSTEP(t + 4, 4); RSTEP(t + 5, 5); RSTEP(t + 6, 6); RSTEP(t + 7, 7);
    }
    RSTEP(4089, 0); RSTEP(4090, 1); RSTEP(4091, 2); RSTEP(4092, 3);
    RSTEP(4093, 4); RSTEP(4094, 5); RSTEP(4095, 6);
}

extern "C" void kernel_launch(void* const* d_in, const int* in_sizes, int n_in,
                              void* d_out, int out_size)
{
    const float* inp  = (const float*)d_in[0];   // inputs (256,4096,3)
    const float* ik   = (const float*)d_in[1];   // input_kernel (3,24)
    const float* rk   = (const float*)d_in[2];   // recurrent_kernel (8,24)
    const float* fk   = (const float*)d_in[3];   // forget_kernel (21,8)
    const float* bias = (const float*)d_in[4];   // bias (32)
    float* out = (float*)d_out;                  // (256,4096,8) f32

    scan_kernel<<<NBATCH, TPB>>>(inp);
    emit_kernel<<<NBATCH * 8, TPB>>>(inp, ik, fk, bias);
    rec_kernel<<<64, 32>>>(rk, out);
}

// round 8
// speedup vs baseline: 1.7129x; 1.0136x over previous
#include <cuda_runtime.h>
#include <cuda_bf16.h>

#define NT 4096
#define NTP 4112       // padded row length (prefetch overrun, no clamping)
#define NBATCH 256
#define TPB 512
#define SPT 8          // time steps per scan thread (4096/512)

// Scratch: [b][u][tp] -> (0.5(xi+bi), xc+bc, 0.5(xo+bo), f); rows padded to NTP
__device__ float4 g_gates[(size_t)NBATCH * 8 * NTP];
// Chunk-exclusive prefix of the 16 L2 accumulators: [b][chunk][16]
__device__ float  g_cbase[(size_t)NBATCH * TPB * 16];

static __device__ __forceinline__ float tanha(float x) {
    float y; asm("tanh.approx.f32 %0, %1;" : "=f"(y) : "f"(x)); return y;
}
static __device__ __forceinline__ float sigm(float x) {
    return fmaf(tanha(0.5f * x), 0.5f, 0.5f);
}

#define FMA4(acc, s, v) do { \
    (acc).x = fmaf((s), (v).x, (acc).x); (acc).y = fmaf((s), (v).y, (acc).y); \
    (acc).z = fmaf((s), (v).z, (acc).z); (acc).w = fmaf((s), (v).w, (acc).w); } while (0)

// ============================================================================
// Kernel 1a: block scan of the 16 L2-term accumulators (chunk granularity).
// ============================================================================
__global__ void __launch_bounds__(TPB) scan_kernel(const float* __restrict__ inp)
{
    __shared__ float wsum[16][16];
    const int b = blockIdx.x, tid = threadIdx.x;
    const float DX0 = 1.0f / 4095.0f;
    const int t0 = tid * SPT;
    const float* __restrict__ xb = inp + (size_t)b * NT * 3;

    float T[16];
#pragma unroll
    for (int c = 0; c < 16; c++) T[c] = 0.f;
    {
        int tm = t0 - 1; if (tm < 0) tm = 0;
        float a0 = xb[tm*3], a1 = xb[tm*3+1], a2 = xb[tm*3+2];
#pragma unroll
        for (int k = 0; k < SPT; k++) {
            const int s = t0 + k;
            const float* p = xb + s * 3;
            float n0 = p[0], n1 = p[1], n2 = p[2];
            const float w = (s >= 1) ? 1.f : 0.f;
            float d1 = (n0-a0)*w, d2 = (n1-a1)*w, d3 = (n2-a2)*w, d0 = DX0*w;
            float pb0 = ((float)s - 0.5f) * DX0;
            float pb1 = 0.5f*(n0+a0), pb2 = 0.5f*(n1+a1), pb3 = 0.5f*(n2+a2);
            T[0] =fmaf(pb0,d0,T[0]);  T[1] =fmaf(pb0,d1,T[1]);  T[2] =fmaf(pb0,d2,T[2]);  T[3] =fmaf(pb0,d3,T[3]);
            T[4] =fmaf(pb1,d0,T[4]);  T[5] =fmaf(pb1,d1,T[5]);  T[6] =fmaf(pb1,d2,T[6]);  T[7] =fmaf(pb1,d3,T[7]);
            T[8] =fmaf(pb2,d0,T[8]);  T[9] =fmaf(pb2,d1,T[9]);  T[10]=fmaf(pb2,d2,T[10]); T[11]=fmaf(pb2,d3,T[11]);
            T[12]=fmaf(pb3,d0,T[12]); T[13]=fmaf(pb3,d1,T[13]); T[14]=fmaf(pb3,d2,T[14]); T[15]=fmaf(pb3,d3,T[15]);
            a0 = n0; a1 = n1; a2 = n2;
        }
    }
    float inc[16];
#pragma unroll
    for (int c = 0; c < 16; c++) inc[c] = T[c];
    const int lane = tid & 31, wid = tid >> 5;
#pragma unroll
    for (int off = 1; off < 32; off <<= 1) {
#pragma unroll
        for (int c = 0; c < 16; c++) {
            float v = __shfl_up_sync(0xffffffffu, inc[c], off);
            if (lane >= off) inc[c] += v;
        }
    }
    if (lane == 31) {
#pragma unroll
        for (int c = 0; c < 16; c++) wsum[wid][c] = inc[c];
    }
    __syncthreads();
    if (tid < 16) {
        float run = 0.f;
        for (int wv = 0; wv < 16; wv++) { float v = wsum[wv][tid]; wsum[wv][tid] = run; run += v; }
    }
    __syncthreads();
    float* __restrict__ cb = g_cbase + ((size_t)b * TPB + tid) * 16;
#pragma unroll
    for (int c = 0; c < 16; c++) cb[c] = wsum[wid][c] + (inc[c] - T[c]);
}

// ============================================================================
// Kernel 1b: one thread per (b, s): rebuild C_s, form signature, emit gates.
// ============================================================================
__global__ void __launch_bounds__(TPB) emit_kernel(
    const float* __restrict__ inp,   // (256, 4096, 3)
    const float* __restrict__ ik,    // (3, 24)
    const float* __restrict__ fk,    // (21, 8)
    const float* __restrict__ bias)  // (32)
{
    __shared__ float4 sF4[42];
    __shared__ float4 sIk4[18];
    __shared__ float4 sB4[8];
    const int tid = threadIdx.x;
    const int b = blockIdx.x >> 3;
    const int s = ((blockIdx.x & 7) << 9) + tid;
    if (tid < 42)      sF4[tid]     = ((const float4*)fk)[tid];
    else if (tid < 60) sIk4[tid-42] = ((const float4*)ik)[tid-42];
    else if (tid < 68) sB4[tid-60]  = ((const float4*)bias)[tid-60];
    __syncthreads();

    const float DX0 = 1.0f / 4095.0f;
    const float* __restrict__ xb = inp + (size_t)b * NT * 3;
    const int j = s >> 3;
    const int t0 = j * SPT;

    float C[16];
    {
        const float* __restrict__ cb = g_cbase + ((size_t)b * TPB + j) * 16;
#pragma unroll
        for (int c = 0; c < 16; c++) C[c] = cb[c];
    }
    {
        int tm = t0 - 1; if (tm < 0) tm = 0;
        float a0 = xb[tm*3], a1 = xb[tm*3+1], a2 = xb[tm*3+2];
#pragma unroll
        for (int k0 = 0; k0 < SPT; k0++) {
            const int k = t0 + k0;
            const float* p = xb + k * 3;
            float n0 = p[0], n1 = p[1], n2 = p[2];
            const float w = (k >= 1 && k <= s) ? 1.f : 0.f;
            float d1 = (n0-a0)*w, d2 = (n1-a1)*w, d3 = (n2-a2)*w, d0 = DX0*w;
            float pb0 = ((float)k - 0.5f) * DX0;
            float pb1 = 0.5f*(n0+a0), pb2 = 0.5f*(n1+a1), pb3 = 0.5f*(n2+a2);
            C[0] =fmaf(pb0,d0,C[0]);  C[1] =fmaf(pb0,d1,C[1]);  C[2] =fmaf(pb0,d2,C[2]);  C[3] =fmaf(pb0,d3,C[3]);
            C[4] =fmaf(pb1,d0,C[4]);  C[5] =fmaf(pb1,d1,C[5]);  C[6] =fmaf(pb1,d2,C[6]);  C[7] =fmaf(pb1,d3,C[7]);
            C[8] =fmaf(pb2,d0,C[8]);  C[9] =fmaf(pb2,d1,C[9]);  C[10]=fmaf(pb2,d2,C[10]); C[11]=fmaf(pb2,d3,C[11]);
            C[12]=fmaf(pb3,d0,C[12]); C[13]=fmaf(pb3,d1,C[13]); C[14]=fmaf(pb3,d2,C[14]); C[15]=fmaf(pb3,d3,C[15]);
            a0 = n0; a1 = n1; a2 = n2;
        }
    }

    const float bx0 = xb[0], bx1 = xb[1], bx2 = xb[2];
    const float xs0 = xb[s*3], xs1 = xb[s*3+1], xs2 = xb[s*3+2];

    float L1_0 = (float)s * DX0;
    float L1_1 = xs0 - bx0, L1_2 = xs1 - bx1, L1_3 = xs2 - bx2;
    float sg[21];
    sg[0] = 1.f;
    sg[1] = L1_0; sg[2] = L1_1; sg[3] = L1_2; sg[4] = L1_3;
    sg[5]  = C[0];                  sg[6]  = C[1];                  sg[7]  = C[2];                  sg[8]  = C[3];
    sg[9]  = fmaf(-bx0,L1_0,C[4]);  sg[10] = fmaf(-bx0,L1_1,C[5]);  sg[11] = fmaf(-bx0,L1_2,C[6]);  sg[12] = fmaf(-bx0,L1_3,C[7]);
    sg[13] = fmaf(-bx1,L1_0,C[8]);  sg[14] = fmaf(-bx1,L1_1,C[9]);  sg[15] = fmaf(-bx1,L1_2,C[10]); sg[16] = fmaf(-bx1,L1_3,C[11]);
    sg[17] = fmaf(-bx2,L1_0,C[12]); sg[18] = fmaf(-bx2,L1_1,C[13]); sg[19] = fmaf(-bx2,L1_2,C[14]); sg[20] = fmaf(-bx2,L1_3,C[15]);
    float norm = 1.0f;
    if (s >= 1) norm = __fdividef(4095.0f, (float)s);
    else {
#pragma unroll
        for (int c2 = 1; c2 < 21; c2++) sg[c2] = 0.f;
    }

    float4 aA = make_float4(0.f,0.f,0.f,0.f), aB = make_float4(0.f,0.f,0.f,0.f);
#pragma unroll
    for (int c2 = 0; c2 < 21; c2++) {
        float sc = sg[c2];
        FMA4(aA, sc, sF4[2*c2]);
        FMA4(aB, sc, sF4[2*c2+1]);
    }
    float fg0 = sigm(fmaf(aA.x, norm, sB4[2].x));
    float fg1 = sigm(fmaf(aA.y, norm, sB4[2].y));
    float fg2 = sigm(fmaf(aA.z, norm, sB4[2].z));
    float fg3 = sigm(fmaf(aA.w, norm, sB4[2].w));
    float fg4 = sigm(fmaf(aB.x, norm, sB4[3].x));
    float fg5 = sigm(fmaf(aB.y, norm, sB4[3].y));
    float fg6 = sigm(fmaf(aB.z, norm, sB4[3].z));
    float fg7 = sigm(fmaf(aB.w, norm, sB4[3].w));

    float4 xiA = sB4[0], xiB = sB4[1], xgA = sB4[4], xgB = sB4[5], xoA = sB4[6], xoB = sB4[7];
    FMA4(xiA, xs0, sIk4[0]);  FMA4(xiB, xs0, sIk4[1]);
    FMA4(xgA, xs0, sIk4[2]);  FMA4(xgB, xs0, sIk4[3]);
    FMA4(xoA, xs0, sIk4[4]);  FMA4(xoB, xs0, sIk4[5]);
    FMA4(xiA, xs1, sIk4[6]);  FMA4(xiB, xs1, sIk4[7]);
    FMA4(xgA, xs1, sIk4[8]);  FMA4(xgB, xs1, sIk4[9]);
    FMA4(xoA, xs1, sIk4[10]); FMA4(xoB, xs1, sIk4[11]);
    FMA4(xiA, xs2, sIk4[12]); FMA4(xiB, xs2, sIk4[13]);
    FMA4(xgA, xs2, sIk4[14]); FMA4(xgB, xs2, sIk4[15]);
    FMA4(xoA, xs2, sIk4[16]); FMA4(xoB, xs2, sIk4[17]);

    float4* __restrict__ gout = g_gates + (size_t)b * 8 * NTP;
    gout[0*NTP + s] = make_float4(0.5f*xiA.x, xgA.x, 0.5f*xoA.x, fg0);
    gout[1*NTP + s] = make_float4(0.5f*xiA.y, xgA.y, 0.5f*xoA.y, fg1);
    gout[2*NTP + s] = make_float4(0.5f*xiA.z, xgA.z, 0.5f*xoA.z, fg2);
    gout[3*NTP + s] = make_float4(0.5f*xiA.w, xgA.w, 0.5f*xoA.w, fg3);
    gout[4*NTP + s] = make_float4(0.5f*xiB.x, xgB.x, 0.5f*xoB.x, fg4);
    gout[5*NTP + s] = make_float4(0.5f*xiB.y, xgB.y, 0.5f*xoB.y, fg5);
    gout[6*NTP + s] = make_float4(0.5f*xiB.z, xgB.z, 0.5f*xoB.z, fg6);
    gout[7*NTP + s] = make_float4(0.5f*xiB.w, xgB.w, 0.5f*xoB.w, fg7);
}

// ============================================================================
// Kernel 2: LSTM recurrence. shfl width-8 broadcast, depth-2 dot trees,
// next-step f*c off-chain, zero per-step integer math (pointer bumps only).
// grid=256 (>=148: avoids low-grid issue throttle), 1 batch per warp.
// ============================================================================
#define RSTEP(J, NJ) do { \
    float h0 = __shfl_sync(0xFFu, h, 0, 8); \
    float h1 = __shfl_sync(0xFFu, h, 1, 8); \
    float h2 = __shfl_sync(0xFFu, h, 2, 8); \
    float h3 = __shfl_sync(0xFFu, h, 3, 8); \
    float h4 = __shfl_sync(0xFFu, h, 4, 8); \
    float h5 = __shfl_sync(0xFFu, h, 5, 8); \
    float h6 = __shfl_sync(0xFFu, h, 6, 8); \
    float h7 = __shfl_sync(0xFFu, h, 7, 8); \
    float4 gt = r##J; \
    r##J = __ldg(gp); gp++; \
    float i0 = fmaf(h1,Ri1, fmaf(h0,Ri0, gt.x)); \
    float i1 = fmaf(h3,Ri3, h2*Ri2); \
    float i2 = fmaf(h5,Ri5, h4*Ri4); \
    float i3 = fmaf(h7,Ri7, h6*Ri6); \
    float c0 = fmaf(h1,Rc1, fmaf(h0,Rc0, gt.y)); \
    float c1 = fmaf(h3,Rc3, h2*Rc2); \
    float c2 = fmaf(h5,Rc5, h4*Rc4); \
    float c3 = fmaf(h7,Rc7, h6*Rc6); \
    float o0 = fmaf(h1,Ro1, fmaf(h0,Ro0, gt.z)); \
    float o1 = fmaf(h3,Ro3, h2*Ro2); \
    float o2 = fmaf(h5,Ro5, h4*Ro4); \
    float o3 = fmaf(h7,Ro7, h6*Ro6); \
    float vi = fmaf(tanha((i0+i1)+(i2+i3)), 0.5f, 0.5f); \
    float vc = tanha((c0+c1)+(c2+c3)); \
    float vo = fmaf(tanha((o0+o1)+(o2+o3)), 0.5f, 0.5f); \
    c = fmaf(vi, vc, fc); \
    fc = r##NJ.w * c;          /* next step's f*c, overlaps tanh(c) */ \
    h = vo * tanha(c); \
    *op = h; op += 8; \
} while (0)

__global__ void __launch_bounds__(32, 1) rec_kernel(
    const float* __restrict__ rk,    // (8, 24)
    float* __restrict__ out)         // (256, 4096, 8)
{
    const int b = blockIdx.x;
    const int u = threadIdx.x;
    if (u >= 8) return;              // 8 active lanes; shfl mask 0xFF width 8

    const float Ri0=0.5f*rk[0*24+u], Ri1=0.5f*rk[1*24+u], Ri2=0.5f*rk[2*24+u], Ri3=0.5f*rk[3*24+u];
    const float Ri4=0.5f*rk[4*24+u], Ri5=0.5f*rk[5*24+u], Ri6=0.5f*rk[6*24+u], Ri7=0.5f*rk[7*24+u];
    const float Rc0=rk[0*24+8+u], Rc1=rk[1*24+8+u], Rc2=rk[2*24+8+u], Rc3=rk[3*24+8+u];
    const float Rc4=rk[4*24+8+u], Rc5=rk[5*24+8+u], Rc6=rk[6*24+8+u], Rc7=rk[7*24+8+u];
    const float Ro0=0.5f*rk[0*24+16+u], Ro1=0.5f*rk[1*24+16+u], Ro2=0.5f*rk[2*24+16+u], Ro3=0.5f*rk[3*24+16+u];
    const float Ro4=0.5f*rk[4*24+16+u], Ro5=0.5f*rk[5*24+16+u], Ro6=0.5f*rk[6*24+16+u], Ro7=0.5f*rk[7*24+16+u];

    const float4* __restrict__ gp = g_gates + ((size_t)b * 8 + u) * NTP;
    float* __restrict__ op = out + (size_t)b * NT * 8 + u;

    float h, c, fc;
    {
        float4 g0 = __ldg(gp);
        float vi = fmaf(tanha(g0.x), 0.5f, 0.5f);
        float vc = tanha(g0.y);
        float vo = fmaf(tanha(g0.z), 0.5f, 0.5f);
        c = vi * vc;
        h = vo * tanha(c);
        *op = h; op += 8;
    }

    float4 r0 = __ldg(gp+1), r1 = __ldg(gp+2), r2 = __ldg(gp+3), r3 = __ldg(gp+4);
    float4 r4 = __ldg(gp+5), r5 = __ldg(gp+6), r6 = __ldg(gp+7), r7 = __ldg(gp+8);
    gp += 9;                         // prefetch target for t = 1 is t+8 = 9
    fc = r0.w * c;                   // f_1 * c_0

    for (int it = 0; it < 511; it++) {
        RSTEP(0,1); RSTEP(1,2); RSTEP(2,3); RSTEP(3,4);
        RSTEP(4,5); RSTEP(5,6); RSTEP(6,7); RSTEP(7,0);
    }
    // tail t = 4089..4095 (slots 0..6); last fc uses garbage slot value, never consumed
    RSTEP(0,1); RSTEP(1,2); RSTEP(2,3); RSTEP(3,4);
    RSTEP(4,5); RSTEP(5,6); RSTEP(6,7);
}

extern "C" void kernel_launch(void* const* d_in, const int* in_sizes, int n_in,
                              void* d_out, int out_size)
{
    const float* inp  = (const float*)d_in[0];   // inputs (256,4096,3)
    const float* ik   = (const float*)d_in[1];   // input_kernel (3,24)
    const float* rk   = (const float*)d_in[2];   // recurrent_kernel (8,24)
    const float* fk   = (const float*)d_in[3];   // forget_kernel (21,8)
    const float* bias = (const float*)d_in[4];   // bias (32)
    float* out = (float*)d_out;                  // (256,4096,8) f32

    scan_kernel<<<NBATCH, TPB>>>(inp);
    emit_kernel<<<NBATCH * 8, TPB>>>(inp, ik, fk, bias);
    rec_kernel<<<NBATCH, 32>>>(rk, out);
}

// round 11
// speedup vs baseline: 2.9485x; 1.7214x over previous
#include <cuda_runtime.h>
#include <cuda_pipeline.h>

#define NT 4096
#define NTPAD 4160     // padded row length (prefetch overrun, no clamping)
#define NBATCH 256
#define TPB 512
#define SPT 8          // time steps per scan thread

// Scratch: [b][u][tpad] -> (0.5(xi+bi), xc+bc, 0.5(xo+bo), f)
__device__ float4 g_gates[(size_t)NBATCH * 8 * NTPAD];
// Chunk-exclusive prefix of the 16 L2 accumulators: [b][chunk][16]
__device__ float  g_cbase[(size_t)NBATCH * TPB * 16];

static __device__ __forceinline__ float tanha(float x) {
    float y; asm("tanh.approx.f32 %0, %1;" : "=f"(y) : "f"(x)); return y;
}
static __device__ __forceinline__ float sigm(float x) {
    return fmaf(tanha(0.5f * x), 0.5f, 0.5f);
}

#define FMA4(acc, s, v) do { \
    (acc).x = fmaf((s), (v).x, (acc).x); (acc).y = fmaf((s), (v).y, (acc).y); \
    (acc).z = fmaf((s), (v).z, (acc).z); (acc).w = fmaf((s), (v).w, (acc).w); } while (0)

// ============================================================================
// Kernel 1a: block scan of the 16 L2-term accumulators (chunk granularity).
// ============================================================================
__global__ void __launch_bounds__(TPB) scan_kernel(const float* __restrict__ inp)
{
    __shared__ float wsum[16][16];
    const int b = blockIdx.x, tid = threadIdx.x;
    const float DX0 = 1.0f / 4095.0f;
    const int t0 = tid * SPT;
    const float* __restrict__ xb = inp + (size_t)b * NT * 3;

    float T[16];
#pragma unroll
    for (int c = 0; c < 16; c++) T[c] = 0.f;
    {
        int tm = t0 - 1; if (tm < 0) tm = 0;
        float a0 = xb[tm*3], a1 = xb[tm*3+1], a2 = xb[tm*3+2];
#pragma unroll
        for (int k = 0; k < SPT; k++) {
            const int s = t0 + k;
            const float* p = xb + s * 3;
            float n0 = p[0], n1 = p[1], n2 = p[2];
            const float w = (s >= 1) ? 1.f : 0.f;
            float d1 = (n0-a0)*w, d2 = (n1-a1)*w, d3 = (n2-a2)*w, d0 = DX0*w;
            float pb0 = ((float)s - 0.5f) * DX0;
            float pb1 = 0.5f*(n0+a0), pb2 = 0.5f*(n1+a1), pb3 = 0.5f*(n2+a2);
            T[0] =fmaf(pb0,d0,T[0]);  T[1] =fmaf(pb0,d1,T[1]);  T[2] =fmaf(pb0,d2,T[2]);  T[3] =fmaf(pb0,d3,T[3]);
            T[4] =fmaf(pb1,d0,T[4]);  T[5] =fmaf(pb1,d1,T[5]);  T[6] =fmaf(pb1,d2,T[6]);  T[7] =fmaf(pb1,d3,T[7]);
            T[8] =fmaf(pb2,d0,T[8]);  T[9] =fmaf(pb2,d1,T[9]);  T[10]=fmaf(pb2,d2,T[10]); T[11]=fmaf(pb2,d3,T[11]);
            T[12]=fmaf(pb3,d0,T[12]); T[13]=fmaf(pb3,d1,T[13]); T[14]=fmaf(pb3,d2,T[14]); T[15]=fmaf(pb3,d3,T[15]);
            a0 = n0; a1 = n1; a2 = n2;
        }
    }
    float inc[16];
#pragma unroll
    for (int c = 0; c < 16; c++) inc[c] = T[c];
    const int lane = tid & 31, wid = tid >> 5;
#pragma unroll
    for (int off = 1; off < 32; off <<= 1) {
#pragma unroll
        for (int c = 0; c < 16; c++) {
            float v = __shfl_up_sync(0xffffffffu, inc[c], off);
            if (lane >= off) inc[c] += v;
        }
    }
    if (lane == 31) {
#pragma unroll
        for (int c = 0; c < 16; c++) wsum[wid][c] = inc[c];
    }
    __syncthreads();
    if (tid < 16) {
        float run = 0.f;
        for (int wv = 0; wv < 16; wv++) { float v = wsum[wv][tid]; wsum[wv][tid] = run; run += v; }
    }
    __syncthreads();
    float* __restrict__ cb = g_cbase + ((size_t)b * TPB + tid) * 16;
#pragma unroll
    for (int c = 0; c < 16; c++) cb[c] = wsum[wid][c] + (inc[c] - T[c]);
}

// ============================================================================
// Kernel 1b: one thread per (b, s): rebuild C_s, form signature, emit gates.
// ============================================================================
__global__ void __launch_bounds__(TPB) emit_kernel(
    const float* __restrict__ inp,   // (256, 4096, 3)
    const float* __restrict__ ik,    // (3, 24)
    const float* __restrict__ fk,    // (21, 8)
    const float* __restrict__ bias)  // (32)
{
    __shared__ float4 sF4[42];
    __shared__ float4 sIk4[18];
    __shared__ float4 sB4[8];
    const int tid = threadIdx.x;
    const int b = blockIdx.x >> 3;
    const int s = ((blockIdx.x & 7) << 9) + tid;
    if (tid < 42)      sF4[tid]     = ((const float4*)fk)[tid];
    else if (tid < 60) sIk4[tid-42] = ((const float4*)ik)[tid-42];
    else if (tid < 68) sB4[tid-60]  = ((const float4*)bias)[tid-60];
    __syncthreads();

    const float DX0 = 1.0f / 4095.0f;
    const float* __restrict__ xb = inp + (size_t)b * NT * 3;
    const int j = s >> 3;
    const int t0 = j * SPT;

    float C[16];
    {
        const float* __restrict__ cb = g_cbase + ((size_t)b * TPB + j) * 16;
#pragma unroll
        for (int c = 0; c < 16; c++) C[c] = cb[c];
    }
    {
        int tm = t0 - 1; if (tm < 0) tm = 0;
        float a0 = xb[tm*3], a1 = xb[tm*3+1], a2 = xb[tm*3+2];
#pragma unroll
        for (int k0 = 0; k0 < SPT; k0++) {
            const int k = t0 + k0;
            const float* p = xb + k * 3;
            float n0 = p[0], n1 = p[1], n2 = p[2];
            const float w = (k >= 1 && k <= s) ? 1.f : 0.f;
            float d1 = (n0-a0)*w, d2 = (n1-a1)*w, d3 = (n2-a2)*w, d0 = DX0*w;
            float pb0 = ((float)k - 0.5f) * DX0;
            float pb1 = 0.5f*(n0+a0), pb2 = 0.5f*(n1+a1), pb3 = 0.5f*(n2+a2);
            C[0] =fmaf(pb0,d0,C[0]);  C[1] =fmaf(pb0,d1,C[1]);  C[2] =fmaf(pb0,d2,C[2]);  C[3] =fmaf(pb0,d3,C[3]);
            C[4] =fmaf(pb1,d0,C[4]);  C[5] =fmaf(pb1,d1,C[5]);  C[6] =fmaf(pb1,d2,C[6]);  C[7] =fmaf(pb1,d3,C[7]);
            C[8] =fmaf(pb2,d0,C[8]);  C[9] =fmaf(pb2,d1,C[9]);  C[10]=fmaf(pb2,d2,C[10]); C[11]=fmaf(pb2,d3,C[11]);
            C[12]=fmaf(pb3,d0,C[12]); C[13]=fmaf(pb3,d1,C[13]); C[14]=fmaf(pb3,d2,C[14]); C[15]=fmaf(pb3,d3,C[15]);
            a0 = n0; a1 = n1; a2 = n2;
        }
    }

    const float bx0 = xb[0], bx1 = xb[1], bx2 = xb[2];
    const float xs0 = xb[s*3], xs1 = xb[s*3+1], xs2 = xb[s*3+2];

    float L1_0 = (float)s * DX0;
    float L1_1 = xs0 - bx0, L1_2 = xs1 - bx1, L1_3 = xs2 - bx2;
    float sg[21];
    sg[0] = 1.f;
    sg[1] = L1_0; sg[2] = L1_1; sg[3] = L1_2; sg[4] = L1_3;
    sg[5]  = C[0];                  sg[6]  = C[1];                  sg[7]  = C[2];                  sg[8]  = C[3];
    sg[9]  = fmaf(-bx0,L1_0,C[4]);  sg[10] = fmaf(-bx0,L1_1,C[5]);  sg[11] = fmaf(-bx0,L1_2,C[6]);  sg[12] = fmaf(-bx0,L1_3,C[7]);
    sg[13] = fmaf(-bx1,L1_0,C[8]);  sg[14] = fmaf(-bx1,L1_1,C[9]);  sg[15] = fmaf(-bx1,L1_2,C[10]); sg[16] = fmaf(-bx1,L1_3,C[11]);
    sg[17] = fmaf(-bx2,L1_0,C[12]); sg[18] = fmaf(-bx2,L1_1,C[13]); sg[19] = fmaf(-bx2,L1_2,C[14]); sg[20] = fmaf(-bx2,L1_3,C[15]);
    float norm = 1.0f;
    if (s >= 1) norm = __fdividef(4095.0f, (float)s);
    else {
#pragma unroll
        for (int c2 = 1; c2 < 21; c2++) sg[c2] = 0.f;
    }

    float4 aA = make_float4(0.f,0.f,0.f,0.f), aB = make_float4(0.f,0.f,0.f,0.f);
#pragma unroll
    for (int c2 = 0; c2 < 21; c2++) {
        float sc = sg[c2];
        FMA4(aA, sc, sF4[2*c2]);
        FMA4(aB, sc, sF4[2*c2+1]);
    }
    float fg0 = sigm(fmaf(aA.x, norm, sB4[2].x));
    float fg1 = sigm(fmaf(aA.y, norm, sB4[2].y));
    float fg2 = sigm(fmaf(aA.z, norm, sB4[2].z));
    float fg3 = sigm(fmaf(aA.w, norm, sB4[2].w));
    float fg4 = sigm(fmaf(aB.x, norm, sB4[3].x));
    float fg5 = sigm(fmaf(aB.y, norm, sB4[3].y));
    float fg6 = sigm(fmaf(aB.z, norm, sB4[3].z));
    float fg7 = sigm(fmaf(aB.w, norm, sB4[3].w));

    float4 xiA = sB4[0], xiB = sB4[1], xgA = sB4[4], xgB = sB4[5], xoA = sB4[6], xoB = sB4[7];
    FMA4(xiA, xs0, sIk4[0]);  FMA4(xiB, xs0, sIk4[1]);
    FMA4(xgA, xs0, sIk4[2]);  FMA4(xgB, xs0, sIk4[3]);
    FMA4(xoA, xs0, sIk4[4]);  FMA4(xoB, xs0, sIk4[5]);
    FMA4(xiA, xs1, sIk4[6]);  FMA4(xiB, xs1, sIk4[7]);
    FMA4(xgA, xs1, sIk4[8]);  FMA4(xgB, xs1, sIk4[9]);
    FMA4(xoA, xs1, sIk4[10]); FMA4(xoB, xs1, sIk4[11]);
    FMA4(xiA, xs2, sIk4[12]); FMA4(xiB, xs2, sIk4[13]);
    FMA4(xgA, xs2, sIk4[14]); FMA4(xgB, xs2, sIk4[15]);
    FMA4(xiA, xs2, make_float4(0.f,0.f,0.f,0.f));   // no-op keep ordering simple
    FMA4(xoA, xs2, sIk4[16]); FMA4(xoB, xs2, sIk4[17]);

    float4* __restrict__ gout = g_gates + (size_t)b * 8 * NTPAD;
    gout[0*NTPAD + s] = make_float4(0.5f*xiA.x, xgA.x, 0.5f*xoA.x, fg0);
    gout[1*NTPAD + s] = make_float4(0.5f*xiA.y, xgA.y, 0.5f*xoA.y, fg1);
    gout[2*NTPAD + s] = make_float4(0.5f*xiA.z, xgA.z, 0.5f*xoA.z, fg2);
    gout[3*NTPAD + s] = make_float4(0.5f*xiA.w, xgA.w, 0.5f*xoA.w, fg3);
    gout[4*NTPAD + s] = make_float4(0.5f*xiB.x, xgB.x, 0.5f*xoB.x, fg4);
    gout[5*NTPAD + s] = make_float4(0.5f*xiB.y, xgB.y, 0.5f*xoB.y, fg5);
    gout[6*NTPAD + s] = make_float4(0.5f*xiB.z, xgB.z, 0.5f*xoB.z, fg6);
    gout[7*NTPAD + s] = make_float4(0.5f*xiB.w, xgB.w, 0.5f*xoB.w, fg7);
}

// ============================================================================
// Kernel 2: LSTM recurrence. Gate stream staged via cp.async double-buffer
// (4 stages x 8 steps) -> per-step load is a conflict-free LDS.128, no LDG
// scoreboard pressure on the chain. Lanes 8-31 participate in copies/shfl,
// stores predicated to lanes 0-7.
// ============================================================================
__global__ void __launch_bounds__(32, 1) rec_kernel(
    const float* __restrict__ rk,    // (8, 24)
    float* __restrict__ out)         // (256, 4096, 8)
{
    __shared__ __align__(16) float4 sbuf[4 * 72];   // stage stride 72, row stride 9 (bank-pad)
    const int b = blockIdx.x;
    const int lane = threadIdx.x;
    const int u = lane & 7;
    const bool active = lane < 8;

    const float Ri0=0.5f*rk[0*24+u], Ri1=0.5f*rk[1*24+u], Ri2=0.5f*rk[2*24+u], Ri3=0.5f*rk[3*24+u];
    const float Ri4=0.5f*rk[4*24+u], Ri5=0.5f*rk[5*24+u], Ri6=0.5f*rk[6*24+u], Ri7=0.5f*rk[7*24+u];
    const float Rc0=rk[0*24+8+u], Rc1=rk[1*24+8+u], Rc2=rk[2*24+8+u], Rc3=rk[3*24+8+u];
    const float Rc4=rk[4*24+8+u], Rc5=rk[5*24+8+u], Rc6=rk[6*24+8+u], Rc7=rk[7*24+8+u];
    const float Ro0=0.5f*rk[0*24+16+u], Ro1=0.5f*rk[1*24+16+u], Ro2=0.5f*rk[2*24+16+u], Ro3=0.5f*rk[3*24+16+u];
    const float Ro4=0.5f*rk[4*24+16+u], Ro5=0.5f*rk[5*24+16+u], Ro6=0.5f*rk[6*24+16+u], Ro7=0.5f*rk[7*24+16+u];

    const float4* __restrict__ gbase = g_gates + (size_t)b * 8 * NTPAD;
    float* __restrict__ op = out + (size_t)b * NT * 8 + u;

    // Copy mapping: element i in [0,64) -> (row cu = i>>3, col ct = i&7).
    // Lane handles i = lane and i = lane+32 (rows cu0 and cu0+4).
    const int cu0 = lane >> 3;
    const int ct0 = lane & 7;
    const float4* __restrict__ src0 = gbase + (size_t)cu0 * NTPAD + ct0;
    const float4* __restrict__ src1 = gbase + (size_t)(cu0 + 4) * NTPAD + ct0;
    float4* const dst0base = &sbuf[cu0 * 9 + ct0];
    float4* const dst1base = &sbuf[(cu0 + 4) * 9 + ct0];

    // prologue: stages 0..2 <- step-blocks 0..2
#pragma unroll
    for (int st = 0; st < 3; st++) {
        __pipeline_memcpy_async(dst0base + st * 72, src0 + st * 8, 16);
        __pipeline_memcpy_async(dst1base + st * 72, src1 + st * 8, 16);
        __pipeline_commit();
    }

    float h = 0.f, c = 0.f;   // t=0 folds in: h=c=0 -> gates = stored x-projections

    for (int bl = 0; bl < 512; bl++) {
        const int st = bl & 3;
        __pipeline_wait_prior(2);
        __syncwarp();
        const float4* __restrict__ sb = sbuf + st * 72 + u * 9;
#pragma unroll
        for (int j = 0; j < 8; j++) {
            float4 gt = sb[j];
            float h0 = __shfl_sync(0xffffffffu, h, 0, 8);
            float h1 = __shfl_sync(0xffffffffu, h, 1, 8);
            float h2 = __shfl_sync(0xffffffffu, h, 2, 8);
            float h3 = __shfl_sync(0xffffffffu, h, 3, 8);
            float h4 = __shfl_sync(0xffffffffu, h, 4, 8);
            float h5 = __shfl_sync(0xffffffffu, h, 5, 8);
            float h6 = __shfl_sync(0xffffffffu, h, 6, 8);
            float h7 = __shfl_sync(0xffffffffu, h, 7, 8);
            float fc = gt.w * c;
            float i0 = fmaf(h1,Ri1, fmaf(h0,Ri0, gt.x));
            float i1 = fmaf(h3,Ri3, h2*Ri2);
            float i2 = fmaf(h5,Ri5, h4*Ri4);
            float i3 = fmaf(h7,Ri7, h6*Ri6);
            float c0 = fmaf(h1,Rc1, fmaf(h0,Rc0, gt.y));
            float c1 = fmaf(h3,Rc3, h2*Rc2);
            float c2 = fmaf(h5,Rc5, h4*Rc4);
            float c3 = fmaf(h7,Rc7, h6*Rc6);
            float o0 = fmaf(h1,Ro1, fmaf(h0,Ro0, gt.z));
            float o1 = fmaf(h3,Ro3, h2*Ro2);
            float o2 = fmaf(h5,Ro5, h4*Ro4);
            float o3 = fmaf(h7,Ro7, h6*Ro6);
            float vi = fmaf(tanha((i0+i1)+(i2+i3)), 0.5f, 0.5f);
            float vc = tanha((c0+c1)+(c2+c3));
            float vo = fmaf(tanha((o0+o1)+(o2+o3)), 0.5f, 0.5f);
            c = fmaf(vi, vc, fc);
            h = vo * tanha(c);
            if (active) *op = h;
            op += 8;
        }
        // prefetch step-block bl+3 into stage (bl+3)&3 (processed stage of iter bl-1)
        const int nst = (bl + 3) & 3;
        const int t0 = (bl + 3) * 8;          // overruns into row padding only (<= 4119 < 4160)
        __pipeline_memcpy_async(dst0base + nst * 72, src0 + t0, 16);
        __pipeline_memcpy_async(dst1base + nst * 72, src1 + t0, 16);
        __pipeline_commit();
    }
}

extern "C" void kernel_launch(void* const* d_in, const int* in_sizes, int n_in,
                              void* d_out, int out_size)
{
    const float* inp  = (const float*)d_in[0];   // inputs (256,4096,3)
    const float* ik   = (const float*)d_in[1];   // input_kernel (3,24)
    const float* rk   = (const float*)d_in[2];   // recurrent_kernel (8,24)
    const float* fk   = (const float*)d_in[3];   // forget_kernel (21,8)
    const float* bias = (const float*)d_in[4];   // bias (32)
    float* out = (float*)d_out;                  // (256,4096,8) f32

    scan_kernel<<<NBATCH, TPB>>>(inp);
    emit_kernel<<<NBATCH * 8, TPB>>>(inp, ik, fk, bias);
    rec_kernel<<<NBATCH, 32>>>(rk, out);
}

// round 12
// speedup vs baseline: 3.1610x; 1.0721x over previous
#include <cuda_runtime.h>
#include <cuda_pipeline.h>

#define NT 4096
#define NTPAD 4224     // padded row length (3-block prefetch overrun, no clamping)
#define NBATCH 256
#define TPB 512
#define SPT 8          // time steps per scan thread

// Scratch: [b][u][tpad] -> (0.5(xi+bi), xc+bc, 0.5(xo+bo), f)
__device__ float4 g_gates[(size_t)NBATCH * 8 * NTPAD];
// Chunk-exclusive prefix of the 16 L2 accumulators: [b][chunk][16]
__device__ float  g_cbase[(size_t)NBATCH * TPB * 16];

static __device__ __forceinline__ float tanha(float x) {
    float y; asm("tanh.approx.f32 %0, %1;" : "=f"(y) : "f"(x)); return y;
}
static __device__ __forceinline__ float sigm(float x) {
    return fmaf(tanha(0.5f * x), 0.5f, 0.5f);
}

#define FMA4(acc, s, v) do { \
    (acc).x = fmaf((s), (v).x, (acc).x); (acc).y = fmaf((s), (v).y, (acc).y); \
    (acc).z = fmaf((s), (v).z, (acc).z); (acc).w = fmaf((s), (v).w, (acc).w); } while (0)

// ============================================================================
// Kernel 1a: block scan of the 16 L2-term accumulators (chunk granularity).
// ============================================================================
__global__ void __launch_bounds__(TPB) scan_kernel(const float* __restrict__ inp)
{
    __shared__ float wsum[16][16];
    const int b = blockIdx.x, tid = threadIdx.x;
    const float DX0 = 1.0f / 4095.0f;
    const int t0 = tid * SPT;
    const float* __restrict__ xb = inp + (size_t)b * NT * 3;

    float T[16];
#pragma unroll
    for (int c = 0; c < 16; c++) T[c] = 0.f;
    {
        int tm = t0 - 1; if (tm < 0) tm = 0;
        float a0 = xb[tm*3], a1 = xb[tm*3+1], a2 = xb[tm*3+2];
#pragma unroll
        for (int k = 0; k < SPT; k++) {
            const int s = t0 + k;
            const float* p = xb + s * 3;
            float n0 = p[0], n1 = p[1], n2 = p[2];
            const float w = (s >= 1) ? 1.f : 0.f;
            float d1 = (n0-a0)*w, d2 = (n1-a1)*w, d3 = (n2-a2)*w, d0 = DX0*w;
            float pb0 = ((float)s - 0.5f) * DX0;
            float pb1 = 0.5f*(n0+a0), pb2 = 0.5f*(n1+a1), pb3 = 0.5f*(n2+a2);
            T[0] =fmaf(pb0,d0,T[0]);  T[1] =fmaf(pb0,d1,T[1]);  T[2] =fmaf(pb0,d2,T[2]);  T[3] =fmaf(pb0,d3,T[3]);
            T[4] =fmaf(pb1,d0,T[4]);  T[5] =fmaf(pb1,d1,T[5]);  T[6] =fmaf(pb1,d2,T[6]);  T[7] =fmaf(pb1,d3,T[7]);
            T[8] =fmaf(pb2,d0,T[8]);  T[9] =fmaf(pb2,d1,T[9]);  T[10]=fmaf(pb2,d2,T[10]); T[11]=fmaf(pb2,d3,T[11]);
            T[12]=fmaf(pb3,d0,T[12]); T[13]=fmaf(pb3,d1,T[13]); T[14]=fmaf(pb3,d2,T[14]); T[15]=fmaf(pb3,d3,T[15]);
            a0 = n0; a1 = n1; a2 = n2;
        }
    }
    float inc[16];
#pragma unroll
    for (int c = 0; c < 16; c++) inc[c] = T[c];
    const int lane = tid & 31, wid = tid >> 5;
#pragma unroll
    for (int off = 1; off < 32; off <<= 1) {
#pragma unroll
        for (int c = 0; c < 16; c++) {
            float v = __shfl_up_sync(0xffffffffu, inc[c], off);
            if (lane >= off) inc[c] += v;
        }
    }
    if (lane == 31) {
#pragma unroll
        for (int c = 0; c < 16; c++) wsum[wid][c] = inc[c];
    }
    __syncthreads();
    if (tid < 16) {
        float run = 0.f;
        for (int wv = 0; wv < 16; wv++) { float v = wsum[wv][tid]; wsum[wv][tid] = run; run += v; }
    }
    __syncthreads();
    float* __restrict__ cb = g_cbase + ((size_t)b * TPB + tid) * 16;
#pragma unroll
    for (int c = 0; c < 16; c++) cb[c] = wsum[wid][c] + (inc[c] - T[c]);
}

// ============================================================================
// Kernel 1b: one thread per (b, s): rebuild C_s, form signature, emit gates.
// ============================================================================
__global__ void __launch_bounds__(TPB) emit_kernel(
    const float* __restrict__ inp,   // (256, 4096, 3)
    const float* __restrict__ ik,    // (3, 24)
    const float* __restrict__ fk,    // (21, 8)
    const float* __restrict__ bias)  // (32)
{
    __shared__ float4 sF4[42];
    __shared__ float4 sIk4[18];
    __shared__ float4 sB4[8];
    const int tid = threadIdx.x;
    const int b = blockIdx.x >> 3;
    const int s = ((blockIdx.x & 7) << 9) + tid;
    if (tid < 42)      sF4[tid]     = ((const float4*)fk)[tid];
    else if (tid < 60) sIk4[tid-42] = ((const float4*)ik)[tid-42];
    else if (tid < 68) sB4[tid-60]  = ((const float4*)bias)[tid-60];
    __syncthreads();

    const float DX0 = 1.0f / 4095.0f;
    const float* __restrict__ xb = inp + (size_t)b * NT * 3;
    const int j = s >> 3;
    const int t0 = j * SPT;

    float C[16];
    {
        const float* __restrict__ cb = g_cbase + ((size_t)b * TPB + j) * 16;
#pragma unroll
        for (int c = 0; c < 16; c++) C[c] = cb[c];
    }
    {
        int tm = t0 - 1; if (tm < 0) tm = 0;
        float a0 = xb[tm*3], a1 = xb[tm*3+1], a2 = xb[tm*3+2];
#pragma unroll
        for (int k0 = 0; k0 < SPT; k0++) {
            const int k = t0 + k0;
            const float* p = xb + k * 3;
            float n0 = p[0], n1 = p[1], n2 = p[2];
            const float w = (k >= 1 && k <= s) ? 1.f : 0.f;
            float d1 = (n0-a0)*w, d2 = (n1-a1)*w, d3 = (n2-a2)*w, d0 = DX0*w;
            float pb0 = ((float)k - 0.5f) * DX0;
            float pb1 = 0.5f*(n0+a0), pb2 = 0.5f*(n1+a1), pb3 = 0.5f*(n2+a2);
            C[0] =fmaf(pb0,d0,C[0]);  C[1] =fmaf(pb0,d1,C[1]);  C[2] =fmaf(pb0,d2,C[2]);  C[3] =fmaf(pb0,d3,C[3]);
            C[4] =fmaf(pb1,d0,C[4]);  C[5] =fmaf(pb1,d1,C[5]);  C[6] =fmaf(pb1,d2,C[6]);  C[7] =fmaf(pb1,d3,C[7]);
            C[8] =fmaf(pb2,d0,C[8]);  C[9] =fmaf(pb2,d1,C[9]);  C[10]=fmaf(pb2,d2,C[10]); C[11]=fmaf(pb2,d3,C[11]);
            C[12]=fmaf(pb3,d0,C[12]); C[13]=fmaf(pb3,d1,C[13]); C[14]=fmaf(pb3,d2,C[14]); C[15]=fmaf(pb3,d3,C[15]);
            a0 = n0; a1 = n1; a2 = n2;
        }
    }

    const float bx0 = xb[0], bx1 = xb[1], bx2 = xb[2];
    const float xs0 = xb[s*3], xs1 = xb[s*3+1], xs2 = xb[s*3+2];

    float L1_0 = (float)s * DX0;
    float L1_1 = xs0 - bx0, L1_2 = xs1 - bx1, L1_3 = xs2 - bx2;
    float sg[21];
    sg[0] = 1.f;
    sg[1] = L1_0; sg[2] = L1_1; sg[3] = L1_2; sg[4] = L1_3;
    sg[5]  = C[0];                  sg[6]  = C[1];                  sg[7]  = C[2];                  sg[8]  = C[3];
    sg[9]  = fmaf(-bx0,L1_0,C[4]);  sg[10] = fmaf(-bx0,L1_1,C[5]);  sg[11] = fmaf(-bx0,L1_2,C[6]);  sg[12] = fmaf(-bx0,L1_3,C[7]);
    sg[13] = fmaf(-bx1,L1_0,C[8]);  sg[14] = fmaf(-bx1,L1_1,C[9]);  sg[15] = fmaf(-bx1,L1_2,C[10]); sg[16] = fmaf(-bx1,L1_3,C[11]);
    sg[17] = fmaf(-bx2,L1_0,C[12]); sg[18] = fmaf(-bx2,L1_1,C[13]); sg[19] = fmaf(-bx2,L1_2,C[14]); sg[20] = fmaf(-bx2,L1_3,C[15]);
    float norm = 1.0f;
    if (s >= 1) norm = __fdividef(4095.0f, (float)s);
    else {
#pragma unroll
        for (int c2 = 1; c2 < 21; c2++) sg[c2] = 0.f;
    }

    float4 aA = make_float4(0.f,0.f,0.f,0.f), aB = make_float4(0.f,0.f,0.f,0.f);
#pragma unroll
    for (int c2 = 0; c2 < 21; c2++) {
        float sc = sg[c2];
        FMA4(aA, sc, sF4[2*c2]);
        FMA4(aB, sc, sF4[2*c2+1]);
    }
    float fg0 = sigm(fmaf(aA.x, norm, sB4[2].x));
    float fg1 = sigm(fmaf(aA.y, norm, sB4[2].y));
    float fg2 = sigm(fmaf(aA.z, norm, sB4[2].z));
    float fg3 = sigm(fmaf(aA.w, norm, sB4[2].w));
    float fg4 = sigm(fmaf(aB.x, norm, sB4[3].x));
    float fg5 = sigm(fmaf(aB.y, norm, sB4[3].y));
    float fg6 = sigm(fmaf(aB.z, norm, sB4[3].z));
    float fg7 = sigm(fmaf(aB.w, norm, sB4[3].w));

    float4 xiA = sB4[0], xiB = sB4[1], xgA = sB4[4], xgB = sB4[5], xoA = sB4[6], xoB = sB4[7];
    FMA4(xiA, xs0, sIk4[0]);  FMA4(xiB, xs0, sIk4[1]);
    FMA4(xgA, xs0, sIk4[2]);  FMA4(xgB, xs0, sIk4[3]);
    FMA4(xoA, xs0, sIk4[4]);  FMA4(xoB, xs0, sIk4[5]);
    FMA4(xiA, xs1, sIk4[6]);  FMA4(xiB, xs1, sIk4[7]);
    FMA4(xgA, xs1, sIk4[8]);  FMA4(xgB, xs1, sIk4[9]);
    FMA4(xoA, xs1, sIk4[10]); FMA4(xoB, xs1, sIk4[11]);
    FMA4(xiA, xs2, sIk4[12]); FMA4(xiB, xs2, sIk4[13]);
    FMA4(xgA, xs2, sIk4[14]); FMA4(xgB, xs2, sIk4[15]);
    FMA4(xoA, xs2, sIk4[16]); FMA4(xoB, xs2, sIk4[17]);

    float4* __restrict__ gout = g_gates + (size_t)b * 8 * NTPAD;
    gout[0*NTPAD + s] = make_float4(0.5f*xiA.x, xgA.x, 0.5f*xoA.x, fg0);
    gout[1*NTPAD + s] = make_float4(0.5f*xiA.y, xgA.y, 0.5f*xoA.y, fg1);
    gout[2*NTPAD + s] = make_float4(0.5f*xiA.z, xgA.z, 0.5f*xoA.z, fg2);
    gout[3*NTPAD + s] = make_float4(0.5f*xiA.w, xgA.w, 0.5f*xoA.w, fg3);
    gout[4*NTPAD + s] = make_float4(0.5f*xiB.x, xgB.x, 0.5f*xoB.x, fg4);
    gout[5*NTPAD + s] = make_float4(0.5f*xiB.y, xgB.y, 0.5f*xoB.y, fg5);
    gout[6*NTPAD + s] = make_float4(0.5f*xiB.z, xgB.z, 0.5f*xoB.z, fg6);
    gout[7*NTPAD + s] = make_float4(0.5f*xiB.w, xgB.w, 0.5f*xoB.w, fg7);
}

// ============================================================================
// Kernel 2: LSTM recurrence. cp.async staging, 4 stages x 32 steps
// (wait/syncwarp/commit amortized over 32 steps). Per-step load = conflict-
// free LDS.128. Skewed add tree (late shfl arrivals shallow).
// ============================================================================
#define STAGE_F4 264    // 8 rows x 33 float4 (row pad -> conflict-free LDS)

__global__ void __launch_bounds__(32, 1) rec_kernel(
    const float* __restrict__ rk,    // (8, 24)
    float* __restrict__ out)         // (256, 4096, 8)
{
    __shared__ __align__(16) float4 sbuf[4 * STAGE_F4];
    const int b = blockIdx.x;
    const int lane = threadIdx.x;
    const int u = lane & 7;
    const bool active = lane < 8;

    const float Ri0=0.5f*rk[0*24+u], Ri1=0.5f*rk[1*24+u], Ri2=0.5f*rk[2*24+u], Ri3=0.5f*rk[3*24+u];
    const float Ri4=0.5f*rk[4*24+u], Ri5=0.5f*rk[5*24+u], Ri6=0.5f*rk[6*24+u], Ri7=0.5f*rk[7*24+u];
    const float Rc0=rk[0*24+8+u], Rc1=rk[1*24+8+u], Rc2=rk[2*24+8+u], Rc3=rk[3*24+8+u];
    const float Rc4=rk[4*24+8+u], Rc5=rk[5*24+8+u], Rc6=rk[6*24+8+u], Rc7=rk[7*24+8+u];
    const float Ro0=0.5f*rk[0*24+16+u], Ro1=0.5f*rk[1*24+16+u], Ro2=0.5f*rk[2*24+16+u], Ro3=0.5f*rk[3*24+16+u];
    const float Ro4=0.5f*rk[4*24+16+u], Ro5=0.5f*rk[5*24+16+u], Ro6=0.5f*rk[6*24+16+u], Ro7=0.5f*rk[7*24+16+u];

    const float4* __restrict__ gbase = g_gates + (size_t)b * 8 * NTPAD;
    float* __restrict__ op = out + (size_t)b * NT * 8 + u;

    // Cooperative copy: lane handles (row k, col lane) for k = 0..7 — but 32
    // lanes cover 8 rows x 32 cols with each lane copying one column slice:
    //   element (k, lane) : k = 0..7  -> 8 cp.async per lane per stage.
    const int ccol = lane;                       // 0..31 (stage has 32 cols)

    // prologue: stages 0..2 <- step-blocks 0..2
#pragma unroll
    for (int st = 0; st < 3; st++) {
#pragma unroll
        for (int k = 0; k < 8; k++) {
            __pipeline_memcpy_async(&sbuf[st * STAGE_F4 + k * 33 + ccol],
                                    gbase + (size_t)k * NTPAD + st * 32 + ccol, 16);
        }
        __pipeline_commit();
    }

    float h = 0.f, c = 0.f;   // t=0 folds in: h=c=0 -> gates = stored x-projections

    for (int bl = 0; bl < 128; bl++) {
        const int st = bl & 3;
        __pipeline_wait_prior(2);
        __syncwarp();
        const float4* __restrict__ sb = sbuf + st * STAGE_F4 + u * 33;
#pragma unroll
        for (int j = 0; j < 32; j++) {
            float4 gt = sb[j];
            float h0 = __shfl_sync(0xffffffffu, h, 0, 8);
            float h1 = __shfl_sync(0xffffffffu, h, 1, 8);
            float h2 = __shfl_sync(0xffffffffu, h, 2, 8);
            float h3 = __shfl_sync(0xffffffffu, h, 3, 8);
            float h4 = __shfl_sync(0xffffffffu, h, 4, 8);
            float h5 = __shfl_sync(0xffffffffu, h, 5, 8);
            float h6 = __shfl_sync(0xffffffffu, h, 6, 8);
            float h7 = __shfl_sync(0xffffffffu, h, 7, 8);
            float fc = gt.w * c;
            // skewed trees: early arrivals (h0..h3) deep, late (h6,h7) shallow
            float i01 = fmaf(h1,Ri1, fmaf(h0,Ri0, gt.x));
            float i23 = fmaf(h3,Ri3, h2*Ri2);
            float i45 = fmaf(h5,Ri5, h4*Ri4);
            float i67 = fmaf(h7,Ri7, h6*Ri6);
            float gi = ((i01 + i23) + i45) + i67;
            float c01 = fmaf(h1,Rc1, fmaf(h0,Rc0, gt.y));
            float c23 = fmaf(h3,Rc3, h2*Rc2);
            float c45 = fmaf(h5,Rc5, h4*Rc4);
            float c67 = fmaf(h7,Rc7, h6*Rc6);
            float gc = ((c01 + c23) + c45) + c67;
            float o01 = fmaf(h1,Ro1, fmaf(h0,Ro0, gt.z));
            float o23 = fmaf(h3,Ro3, h2*Ro2);
            float o45 = fmaf(h5,Ro5, h4*Ro4);
            float o67 = fmaf(h7,Ro7, h6*Ro6);
            float go = ((o01 + o23) + o45) + o67;
            float vi = fmaf(tanha(gi), 0.5f, 0.5f);
            float vc = tanha(gc);
            float vo = fmaf(tanha(go), 0.5f, 0.5f);
            c = fmaf(vi, vc, fc);
            h = vo * tanha(c);
            if (active) *op = h;
            op += 8;
        }
        // prefetch step-block bl+3 into stage (bl+3)&3
        const int nst = (bl + 3) & 3;
        const int t0 = (bl + 3) * 32;         // max 4192+31 = 4223 < NTPAD
#pragma unroll
        for (int k = 0; k < 8; k++) {
            __pipeline_memcpy_async(&sbuf[nst * STAGE_F4 + k * 33 + ccol],
                                    gbase + (size_t)k * NTPAD + t0 + ccol, 16);
        }
        __pipeline_commit();
    }
}

extern "C" void kernel_launch(void* const* d_in, const int* in_sizes, int n_in,
                              void* d_out, int out_size)
{
    const float* inp  = (const float*)d_in[0];   // inputs (256,4096,3)
    const float* ik   = (const float*)d_in[1];   // input_kernel (3,24)
    const float* rk   = (const float*)d_in[2];   // recurrent_kernel (8,24)
    const float* fk   = (const float*)d_in[3];   // forget_kernel (21,8)
    const float* bias = (const float*)d_in[4];   // bias (32)
    float* out = (float*)d_out;                  // (256,4096,8) f32

    scan_kernel<<<NBATCH, TPB>>>(inp);
    emit_kernel<<<NBATCH * 8, TPB>>>(inp, ik, fk, bias);
    rec_kernel<<<NBATCH, 32>>>(rk, out);
}